// round 14
// baseline (speedup 1.0000x reference)
#include <cuda_runtime.h>
#include <cuda_bf16.h>
#include <math.h>
#include <stdint.h>

// Shapes: N=50000 atoms (D=64), E=1.6M edges, W[192][128]
#define MAXN 50000
#define MAXE 1600000
#define NREP 128

// Interleaved column convention ("pos" order), m = 0..63 message col:
//   pos 2m   = z/P column m        (filter half)
//   pos 2m+1 = z/P column 64+m     (core half)
__device__ float  g_P[(size_t)MAXN * 256];
__device__ float  g_z[(size_t)MAXE * 128];
__device__ float  g_upd[(size_t)MAXN * 64];  // original message-col order
__device__ float  g_stat[NREP][256];
__device__ double g_s2[128];                 // BN2: [0..63 sum, 64..127 sumsq]
__device__ float  g_scale1[128], g_shift1[128];   // pos order
__device__ float  g_scale2[64],  g_shift2[64];
__device__ uint4  g_wf[2048];                // W3 mma B frags interleaved (h0,h1,l0,l1)

__device__ __forceinline__ float softplusf(float x) {
    return fmaxf(x, 0.0f) + log1pf(expf(-fabsf(x)));
}
__device__ __forceinline__ float sigmoidf(float x) {
    return 1.0f / (1.0f + expf(-x));
}
__device__ __forceinline__ uint32_t packbf(float a, float b) {
    __nv_bfloat162 t = __halves2bfloat162(__float2bfloat16(a), __float2bfloat16(b));
    return *reinterpret_cast<uint32_t*>(&t);
}

#define MMA_BF16(c, a, b0, b1)                                              \
    asm volatile(                                                           \
        "mma.sync.aligned.m16n8k16.row.col.f32.bf16.bf16.f32 "              \
        "{%0,%1,%2,%3}, {%4,%5,%6,%7}, {%8,%9}, {%0,%1,%2,%3};"             \
        : "+f"((c)[0]), "+f"((c)[1]), "+f"((c)[2]), "+f"((c)[3])            \
        : "r"((a)[0]), "r"((a)[1]), "r"((a)[2]), "r"((a)[3]),               \
          "r"(b0), "r"(b1))

// ---------------------------------------------------------------- K0: zero scratch
__global__ void k_zero(int N) {
    int t = blockIdx.x * blockDim.x + threadIdx.x;
    if (t < NREP * 256) ((float*)g_stat)[t] = 0.0f;
    if (t < 128) g_s2[t] = 0.0;
    int total = N * 64;
    int stride = gridDim.x * blockDim.x;
    for (int i = t; i < total; i += stride) g_upd[i] = 0.0f;
}

// ---------------------------------------------------------------- K0b: W3 -> interleaved hi/lo B frags
__global__ void k_prepW(const float* __restrict__ W) {
    int tid = blockIdx.x * blockDim.x + threadIdx.x;
    if (tid >= 2048) return;
    int lane = tid & 31, nt = (tid >> 5) & 15, kk = tid >> 9;
    int g = lane >> 2, tig = lane & 3;
    int n = 8 * nt + g;
    int k0 = 16 * kk + 2 * tig;
    float w0 = W[(128 + k0) * 128 + n];
    float w1 = W[(128 + k0 + 1) * 128 + n];
    float w8 = W[(128 + k0 + 8) * 128 + n];
    float w9 = W[(128 + k0 + 9) * 128 + n];
    uint32_t h0 = packbf(w0, w1);
    uint32_t h1 = packbf(w8, w9);
    __nv_bfloat162 hh0 = *reinterpret_cast<__nv_bfloat162*>(&h0);
    __nv_bfloat162 hh1 = *reinterpret_cast<__nv_bfloat162*>(&h1);
    uint32_t l0 = packbf(w0 - __bfloat162float(hh0.x), w1 - __bfloat162float(hh0.y));
    uint32_t l1 = packbf(w8 - __bfloat162float(hh1.x), w9 - __bfloat162float(hh1.y));
    g_wf[tid] = make_uint4(h0, h1, l0, l1);
}

// ---------------------------------------------------------------- K1: P1/P2 precompute (FFMA; small)
__global__ void k_precompute(const float* __restrict__ atom,
                             const float* __restrict__ W,
                             const float* __restrict__ b, int N) {
    __shared__ float As[32 * 128];
    __shared__ float Bs[64 * 128];
    const int half = blockIdx.x;
    const int ab = blockIdx.y * 128;
    const int tid = threadIdx.x;

    for (int i = tid; i < 64 * 128; i += 256) {
        int k = i >> 7, p = i & 127;
        int colm = (p & 1) ? 64 + (p >> 1) : (p >> 1);   // pos -> original column
        Bs[i] = W[(half * 64 + k) * 128 + colm];
    }

    const int ty = tid >> 4, tx = tid & 15;
    const int r0 = ty * 8, c0 = tx * 8;
    float acc[64];
#pragma unroll
    for (int i = 0; i < 64; i++) acc[i] = 0.0f;

    for (int kk = 0; kk < 64; kk += 32) {
        for (int li = tid; li < 1024; li += 256) {
            int row = li >> 3, kq = (li & 7) * 4;
            float4 v = make_float4(0.f, 0.f, 0.f, 0.f);
            if (ab + row < N)
                v = *(const float4*)&atom[(size_t)(ab + row) * 64 + kk + kq];
            As[(kq + 0) * 128 + row] = v.x;
            As[(kq + 1) * 128 + row] = v.y;
            As[(kq + 2) * 128 + row] = v.z;
            As[(kq + 3) * 128 + row] = v.w;
        }
        __syncthreads();
#pragma unroll 8
        for (int k = 0; k < 32; ++k) {
            const float* Ak = &As[k * 128];
            const float* Bk = &Bs[(kk + k) * 128];
            float4 a0 = *(const float4*)(Ak + r0);
            float4 a1 = *(const float4*)(Ak + r0 + 4);
            float4 b0 = *(const float4*)(Bk + c0);
            float4 b1 = *(const float4*)(Bk + c0 + 4);
            float av[8] = {a0.x, a0.y, a0.z, a0.w, a1.x, a1.y, a1.z, a1.w};
            float bv[8] = {b0.x, b0.y, b0.z, b0.w, b1.x, b1.y, b1.z, b1.w};
#pragma unroll
            for (int i = 0; i < 8; i++)
#pragma unroll
                for (int j = 0; j < 8; j++)
                    acc[i * 8 + j] = fmaf(av[i], bv[j], acc[i * 8 + j]);
        }
        __syncthreads();
    }

    float bias[8];
#pragma unroll
    for (int j = 0; j < 8; j++) {
        int p = c0 + j;
        int colm = (p & 1) ? 64 + (p >> 1) : (p >> 1);
        bias[j] = (half == 0) ? b[colm] : 0.0f;
    }

#pragma unroll
    for (int i = 0; i < 8; i++) {
        int row = ab + r0 + i;
        if (row < N) {
            float* dst = &g_P[(size_t)row * 256 + half * 128 + c0];
            *(float4*)(dst)     = make_float4(acc[i*8+0]+bias[0], acc[i*8+1]+bias[1],
                                              acc[i*8+2]+bias[2], acc[i*8+3]+bias[3]);
            *(float4*)(dst + 4) = make_float4(acc[i*8+4]+bias[4], acc[i*8+5]+bias[5],
                                              acc[i*8+6]+bias[6], acc[i*8+7]+bias[7]);
        }
    }
}

// ---------------------------------------------------------------- K2: HMMA edge GEMM + gather + z + stats
// A fragments staged in SMEM (coalesced gmem read + fragment-layout STS),
// mainloop reads A via LDS.128 per kk -> only 8 A regs live; acc[64] dominates.
// Dynamic smem: [0,32K) W frags, [32K,48K) Ah, [48K,64K) Al.
__global__ void __launch_bounds__(256, 3) k_edge_mma(const float* __restrict__ nbr,
                                                     const int* __restrict__ esrc,
                                                     const int* __restrict__ edst, int E) {
    extern __shared__ char smem[];
    uint4* s_w  = (uint4*)smem;                       // 2048 uint4
    uint32_t* s_ah = (uint32_t*)(smem + 32768);       // 4096 u32
    uint32_t* s_al = (uint32_t*)(smem + 49152);       // 4096 u32

    const int tid = threadIdx.x, lane = tid & 31, w = tid >> 5;
    const int g = lane >> 2, tig = lane & 3;

    for (int i = tid; i < 2048; i += 256) s_w[i] = g_wf[i];

    // ---- stage A: thread t -> edge e = t>>1, row-half hf = t&1 (32 floats, coalesced) ----
    {
        int e = tid >> 1, hf = tid & 1;
        int ge = blockIdx.x * 128 + e;
        bool v = ge < E;
        const float4* row = (const float4*)(nbr + (size_t)ge * 64 + hf * 32);
        int w_ = e >> 4, esub = e & 15;
        int g_ = esub & 7, side = esub >> 3;
#pragma unroll
        for (int j = 0; j < 8; j++) {
            float4 x = v ? row[j] : make_float4(0.f, 0.f, 0.f, 0.f);
#pragma unroll
            for (int half2 = 0; half2 < 2; half2++) {
                float a = half2 ? x.z : x.x;
                float b = half2 ? x.w : x.y;
                int p = 16 * hf + 2 * j + half2;       // k-pair index 0..31
                int kk = p >> 3, q = p & 7;
                int tg = (q < 4) ? q : q - 4;
                int r = ((q >= 4) ? 2 : 0) + side;
                int idx = (((w_ * 4 + kk) * 32) + 4 * g_ + tg) * 4 + r;
                uint32_t h = packbf(a, b);
                __nv_bfloat162 t2 = *reinterpret_cast<__nv_bfloat162*>(&h);
                s_ah[idx] = h;
                s_al[idx] = packbf(a - __bfloat162float(t2.x), b - __bfloat162float(t2.y));
            }
        }
    }
    __syncthreads();

    const int e0 = blockIdx.x * 128 + w * 16 + g;
    const int e1 = e0 + 8;
    const bool v0 = e0 < E, v1 = e1 < E;

    // ---- mma mainloop: A from smem per kk (8 regs), B from smem ----
    float acc[64];
#pragma unroll
    for (int i = 0; i < 64; i++) acc[i] = 0.0f;

    const uint4* s_ah4 = (const uint4*)s_ah;
    const uint4* s_al4 = (const uint4*)s_al;
#pragma unroll
    for (int kk = 0; kk < 4; kk++) {
        uint4 ahv = s_ah4[(w * 4 + kk) * 32 + lane];
        uint4 alv = s_al4[(w * 4 + kk) * 32 + lane];
        uint32_t ah[4] = {ahv.x, ahv.y, ahv.z, ahv.w};
        uint32_t al[4] = {alv.x, alv.y, alv.z, alv.w};
#pragma unroll
        for (int nt = 0; nt < 16; nt++) {
            float* c = acc + nt * 4;
            uint4 bw = s_w[(kk * 16 + nt) * 32 + lane];
            MMA_BF16(c, ah, bw.x, bw.y);   // Ah * Bh
            MMA_BF16(c, al, bw.x, bw.y);   // Al * Bh
            MMA_BF16(c, ah, bw.z, bw.w);   // Ah * Bl
        }
    }

    // ---- epilogue (interleaved pos layout, identical to the 599us version) ----
    int s0 = 0, d0 = 0, s1 = 0, d1 = 0;
    if (v0) { s0 = esrc[e0]; d0 = edst[e0]; }
    if (v1) { s1 = esrc[e1]; d1 = edst[e1]; }
    const int rep = (blockIdx.x ^ g) & (NREP - 1);
    float* gstat = g_stat[rep];

#pragma unroll
    for (int nt = 0; nt < 8; nt++) {
        const int i0 = 16 * nt + 4 * tig;
        float f0a = 0.f, c0a = 0.f, f1a = 0.f, c1a = 0.f;   // edge e0
        float f0b = 0.f, c0b = 0.f, f1b = 0.f, c1b = 0.f;   // edge e1
        if (v0) {
            float4 p1 = *(const float4*)&g_P[(size_t)s0 * 256 + i0];
            float4 p2 = *(const float4*)&g_P[(size_t)d0 * 256 + 128 + i0];
            f0a = acc[nt*4+0]     + p1.x + p2.x;
            c0a = acc[(nt+8)*4+0] + p1.y + p2.y;
            f1a = acc[nt*4+1]     + p1.z + p2.z;
            c1a = acc[(nt+8)*4+1] + p1.w + p2.w;
            *(float4*)&g_z[(size_t)e0 * 128 + i0] = make_float4(f0a, c0a, f1a, c1a);
        }
        if (v1) {
            float4 p1 = *(const float4*)&g_P[(size_t)s1 * 256 + i0];
            float4 p2 = *(const float4*)&g_P[(size_t)d1 * 256 + 128 + i0];
            f0b = acc[nt*4+2]     + p1.x + p2.x;
            c0b = acc[(nt+8)*4+2] + p1.y + p2.y;
            f1b = acc[nt*4+3]     + p1.z + p2.z;
            c1b = acc[(nt+8)*4+3] + p1.w + p2.w;
            *(float4*)&g_z[(size_t)e1 * 128 + i0] = make_float4(f0b, c0b, f1b, c1b);
        }
        float sf0 = f0a + f0b, qf0 = f0a * f0a + f0b * f0b;
        float sc0 = c0a + c0b, qc0 = c0a * c0a + c0b * c0b;
        float sf1 = f1a + f1b, qf1 = f1a * f1a + f1b * f1b;
        float sc1 = c1a + c1b, qc1 = c1a * c1a + c1b * c1b;
        asm volatile("red.global.add.v4.f32 [%0], {%1, %2, %3, %4};"
                     :: "l"(gstat + 2 * i0),     "f"(sf0), "f"(qf0), "f"(sc0), "f"(qc0) : "memory");
        asm volatile("red.global.add.v4.f32 [%0], {%1, %2, %3, %4};"
                     :: "l"(gstat + 2 * i0 + 4), "f"(sf1), "f"(qf1), "f"(sc1), "f"(qc1) : "memory");
    }
}

// ---------------------------------------------------------------- K3: BN1 finalize (emits pos-order scale/shift)
__global__ void k_bn1(const float* __restrict__ g1, const float* __restrict__ b1, int E) {
    int j = threadIdx.x;  // original column 0..127
    int base = (j < 64) ? 4 * j : 4 * (j - 64) + 2;
    double s = 0.0, q = 0.0;
    for (int r = 0; r < NREP; r++) {
        s += (double)g_stat[r][base];
        q += (double)g_stat[r][base + 1];
    }
    double mean = s / (double)E;
    double var  = q / (double)E - mean * mean;
    float istd = (float)rsqrt(var + 1e-5);
    float sc = g1[j] * istd;
    int pos = (j < 64) ? 2 * j : 2 * (j - 64) + 1;
    g_scale1[pos] = sc;
    g_shift1[pos] = b1[j] - (float)mean * sc;
}

// ---------------------------------------------------------------- K4: BN1 + gated message + scatter
__global__ void k_msg(const int* __restrict__ edst, int E) {
    int gw = (int)((blockIdx.x * (size_t)blockDim.x + threadIdx.x) >> 5);
    int lane = threadIdx.x & 31;
    if (gw >= E) return;
    float4 zv = *(const float4*)&g_z[(size_t)gw * 128 + 4 * lane];
    float4 sc = *(const float4*)&g_scale1[4 * lane];
    float4 sh = *(const float4*)&g_shift1[4 * lane];
    float m0 = sigmoidf(zv.x * sc.x + sh.x) * softplusf(zv.y * sc.y + sh.y);
    float m1 = sigmoidf(zv.z * sc.z + sh.z) * softplusf(zv.w * sc.w + sh.w);
    float sm0 = __shfl_xor_sync(0xFFFFFFFFu, m0, 1);
    float sm1 = __shfl_xor_sync(0xFFFFFFFFu, m1, 1);
    if ((lane & 1) == 0) {
        int d = edst[gw];
        float* p = &g_upd[(size_t)d * 64 + 2 * lane];
        asm volatile("red.global.add.v4.f32 [%0], {%1,%2,%3,%4};"
                     :: "l"(p), "f"(m0), "f"(m1), "f"(sm0), "f"(sm1) : "memory");
    }
}

// ---------------------------------------------------------------- K5: BN2 stats
__global__ void k_stats2(int N) {
    __shared__ double ssum[64], ssq[64];
    int tid = threadIdx.x;  // 256
    if (tid < 64) { ssum[tid] = 0.0; ssq[tid] = 0.0; }
    __syncthreads();
    int col = tid & 63;
    int r = blockIdx.x * 4 + (tid >> 6);
    float s = 0.0f, q = 0.0f;
    for (; r < N; r += gridDim.x * 4) {
        float v = g_upd[(size_t)r * 64 + col];
        s += v; q += v * v;
    }
    atomicAdd(&ssum[col], (double)s);
    atomicAdd(&ssq[col], (double)q);
    __syncthreads();
    if (tid < 64) {
        atomicAdd(&g_s2[tid], ssum[tid]);
        atomicAdd(&g_s2[64 + tid], ssq[tid]);
    }
}

// ---------------------------------------------------------------- K6: BN2 finalize
__global__ void k_bn2(const float* __restrict__ g2, const float* __restrict__ b2, int N) {
    int j = threadIdx.x;  // 64
    double mean = g_s2[j] / (double)N;
    double var  = g_s2[64 + j] / (double)N - mean * mean;
    float istd = (float)rsqrt(var + 1e-5);
    float sc = g2[j] * istd;
    g_scale2[j] = sc;
    g_shift2[j] = b2[j] - (float)mean * sc;
}

// ---------------------------------------------------------------- K7: output
__global__ void k_out(const float* __restrict__ atom, float* __restrict__ out, int N) {
    int i = blockIdx.x * blockDim.x + threadIdx.x;
    int total = N * 64;
    if (i >= total) return;
    int col = i & 63;
    float u = g_upd[i] * g_scale2[col] + g_shift2[col];
    out[i] = softplusf(atom[i] + u);
}

// ----------------------------------------------------------------
extern "C" void kernel_launch(void* const* d_in, const int* in_sizes, int n_in,
                              void* d_out, int out_size) {
    const float* atom = (const float*)d_in[0];
    const float* nbr  = (const float*)d_in[1];
    const int*   esrc = (const int*)d_in[2];
    const int*   edst = (const int*)d_in[3];
    const float* W    = (const float*)d_in[4];
    const float* b    = (const float*)d_in[5];
    const float* bn1g = (const float*)d_in[6];
    const float* bn1b = (const float*)d_in[7];
    const float* bn2g = (const float*)d_in[8];
    const float* bn2b = (const float*)d_in[9];
    float* out = (float*)d_out;

    int N = in_sizes[0] / 64;
    int E = in_sizes[2];
    int gE = (E + 127) / 128;

    static int smem_set = 0;
    if (!smem_set) {
        cudaFuncSetAttribute(k_edge_mma, cudaFuncAttributeMaxDynamicSharedMemorySize, 65536);
        smem_set = 1;
    }

    k_zero<<<2048, 256>>>(N);
    k_prepW<<<8, 256>>>(W);
    dim3 gP(2, (N + 127) / 128);
    k_precompute<<<gP, 256>>>(atom, W, b, N);
    k_edge_mma<<<gE, 256, 65536>>>(nbr, esrc, edst, E);
    k_bn1<<<1, 128>>>(bn1g, bn1b, E);
    {
        long long threads = (long long)E * 32;
        int grid = (int)((threads + 255) / 256);
        k_msg<<<grid, 256>>>(edst, E);
    }
    k_stats2<<<128, 256>>>(N);
    k_bn2<<<1, 64>>>(bn2g, bn2b, N);
    k_out<<<(N * 64 + 255) / 256, 256>>>(atom, out, N);
}

// round 15
// speedup vs baseline: 1.2260x; 1.2260x over previous
#include <cuda_runtime.h>
#include <cuda_bf16.h>
#include <cuda_fp16.h>
#include <math.h>
#include <stdint.h>

// Shapes: N=50000 atoms (D=64), E=1.6M edges, W[192][128]
#define MAXN 50000
#define MAXE 1600000
#define NREP 128

// Interleaved column convention ("pos" order), m = 0..63 message col:
//   pos 2m   = z/P column m        (filter half)
//   pos 2m+1 = z/P column 64+m     (core half)
__device__ float  g_P[(size_t)MAXN * 256];
__device__ __half g_zh[(size_t)MAXE * 128];  // fp16 z, pos order
__device__ float  g_upd[(size_t)MAXN * 64];  // original message-col order
__device__ float  g_stat[NREP][256];
__device__ double g_s2[128];                 // BN2: [0..63 sum, 64..127 sumsq]
__device__ float  g_scale1[128], g_shift1[128];   // pos order
__device__ float  g_scale2[64],  g_shift2[64];
__device__ uint4  g_wf[2048];                // W3 mma B frags interleaved (h0,h1,l0,l1)

__device__ __forceinline__ float softplusf(float x) {
    return fmaxf(x, 0.0f) + log1pf(expf(-fabsf(x)));
}
__device__ __forceinline__ float sigmoidf(float x) {
    return 1.0f / (1.0f + expf(-x));
}
__device__ __forceinline__ uint32_t packbf(float a, float b) {
    __nv_bfloat162 t = __halves2bfloat162(__float2bfloat16(a), __float2bfloat16(b));
    return *reinterpret_cast<uint32_t*>(&t);
}
__device__ __forceinline__ uint32_t packh2(float a, float b) {
    __half2 t = __floats2half2_rn(a, b);
    return *reinterpret_cast<uint32_t*>(&t);
}

#define MMA_BF16(c, a, b0, b1)                                              \
    asm volatile(                                                           \
        "mma.sync.aligned.m16n8k16.row.col.f32.bf16.bf16.f32 "              \
        "{%0,%1,%2,%3}, {%4,%5,%6,%7}, {%8,%9}, {%0,%1,%2,%3};"             \
        : "+f"((c)[0]), "+f"((c)[1]), "+f"((c)[2]), "+f"((c)[3])            \
        : "r"((a)[0]), "r"((a)[1]), "r"((a)[2]), "r"((a)[3]),               \
          "r"(b0), "r"(b1))

// ---------------------------------------------------------------- K0: zero scratch
__global__ void k_zero(int N) {
    int t = blockIdx.x * blockDim.x + threadIdx.x;
    if (t < NREP * 256) ((float*)g_stat)[t] = 0.0f;
    if (t < 128) g_s2[t] = 0.0;
    int total = N * 64;
    int stride = gridDim.x * blockDim.x;
    for (int i = t; i < total; i += stride) g_upd[i] = 0.0f;
}

// ---------------------------------------------------------------- K0b: W3 -> interleaved hi/lo B frags
__global__ void k_prepW(const float* __restrict__ W) {
    int tid = blockIdx.x * blockDim.x + threadIdx.x;
    if (tid >= 2048) return;
    int lane = tid & 31, nt = (tid >> 5) & 15, kk = tid >> 9;
    int g = lane >> 2, tig = lane & 3;
    int n = 8 * nt + g;
    int k0 = 16 * kk + 2 * tig;
    float w0 = W[(128 + k0) * 128 + n];
    float w1 = W[(128 + k0 + 1) * 128 + n];
    float w8 = W[(128 + k0 + 8) * 128 + n];
    float w9 = W[(128 + k0 + 9) * 128 + n];
    uint32_t h0 = packbf(w0, w1);
    uint32_t h1 = packbf(w8, w9);
    __nv_bfloat162 hh0 = *reinterpret_cast<__nv_bfloat162*>(&h0);
    __nv_bfloat162 hh1 = *reinterpret_cast<__nv_bfloat162*>(&h1);
    uint32_t l0 = packbf(w0 - __bfloat162float(hh0.x), w1 - __bfloat162float(hh0.y));
    uint32_t l1 = packbf(w8 - __bfloat162float(hh1.x), w9 - __bfloat162float(hh1.y));
    g_wf[tid] = make_uint4(h0, h1, l0, l1);
}

// ---------------------------------------------------------------- K1: P1/P2 precompute (FFMA; small)
__global__ void k_precompute(const float* __restrict__ atom,
                             const float* __restrict__ W,
                             const float* __restrict__ b, int N) {
    __shared__ float As[32 * 128];
    __shared__ float Bs[64 * 128];
    const int half = blockIdx.x;
    const int ab = blockIdx.y * 128;
    const int tid = threadIdx.x;

    for (int i = tid; i < 64 * 128; i += 256) {
        int k = i >> 7, p = i & 127;
        int colm = (p & 1) ? 64 + (p >> 1) : (p >> 1);   // pos -> original column
        Bs[i] = W[(half * 64 + k) * 128 + colm];
    }

    const int ty = tid >> 4, tx = tid & 15;
    const int r0 = ty * 8, c0 = tx * 8;
    float acc[64];
#pragma unroll
    for (int i = 0; i < 64; i++) acc[i] = 0.0f;

    for (int kk = 0; kk < 64; kk += 32) {
        for (int li = tid; li < 1024; li += 256) {
            int row = li >> 3, kq = (li & 7) * 4;
            float4 v = make_float4(0.f, 0.f, 0.f, 0.f);
            if (ab + row < N)
                v = *(const float4*)&atom[(size_t)(ab + row) * 64 + kk + kq];
            As[(kq + 0) * 128 + row] = v.x;
            As[(kq + 1) * 128 + row] = v.y;
            As[(kq + 2) * 128 + row] = v.z;
            As[(kq + 3) * 128 + row] = v.w;
        }
        __syncthreads();
#pragma unroll 8
        for (int k = 0; k < 32; ++k) {
            const float* Ak = &As[k * 128];
            const float* Bk = &Bs[(kk + k) * 128];
            float4 a0 = *(const float4*)(Ak + r0);
            float4 a1 = *(const float4*)(Ak + r0 + 4);
            float4 b0 = *(const float4*)(Bk + c0);
            float4 b1 = *(const float4*)(Bk + c0 + 4);
            float av[8] = {a0.x, a0.y, a0.z, a0.w, a1.x, a1.y, a1.z, a1.w};
            float bv[8] = {b0.x, b0.y, b0.z, b0.w, b1.x, b1.y, b1.z, b1.w};
#pragma unroll
            for (int i = 0; i < 8; i++)
#pragma unroll
                for (int j = 0; j < 8; j++)
                    acc[i * 8 + j] = fmaf(av[i], bv[j], acc[i * 8 + j]);
        }
        __syncthreads();
    }

    float bias[8];
#pragma unroll
    for (int j = 0; j < 8; j++) {
        int p = c0 + j;
        int colm = (p & 1) ? 64 + (p >> 1) : (p >> 1);
        bias[j] = (half == 0) ? b[colm] : 0.0f;
    }

#pragma unroll
    for (int i = 0; i < 8; i++) {
        int row = ab + r0 + i;
        if (row < N) {
            float* dst = &g_P[(size_t)row * 256 + half * 128 + c0];
            *(float4*)(dst)     = make_float4(acc[i*8+0]+bias[0], acc[i*8+1]+bias[1],
                                              acc[i*8+2]+bias[2], acc[i*8+3]+bias[3]);
            *(float4*)(dst + 4) = make_float4(acc[i*8+4]+bias[4], acc[i*8+5]+bias[5],
                                              acc[i*8+6]+bias[6], acc[i*8+7]+bias[7]);
        }
    }
}

// ---------------------------------------------------------------- K2: HMMA edge GEMM + gather + z(fp16) + stats
// R10 structure (front-batched A, regs ~90) with:
//  - kk-outer / nt-inner MMA order (breaks 12-deep accumulator chains, A loads unchanged)
//  - z stored fp16 (half the write bytes)
__global__ void __launch_bounds__(256, 1) k_edge_mma(const float* __restrict__ nbr,
                                                     const int* __restrict__ esrc,
                                                     const int* __restrict__ edst, int E) {
    __shared__ uint4 s_w[2048];
    const int tid = threadIdx.x, lane = tid & 31, w = tid >> 5;
    const int g = lane >> 2, tig = lane & 3;

    for (int i = tid; i < 2048; i += 256) s_w[i] = g_wf[i];

    const int e0 = blockIdx.x * 128 + w * 16 + g;
    const int e1 = e0 + 8;
    const bool v0 = e0 < E, v1 = e1 < E;

    // ---- load A fragments straight from gmem, split into bf16 hi/lo (front-batched) ----
    uint32_t ah[16], al[16];
    {
        const float* r0 = nbr + (size_t)e0 * 64;
        const float* r1 = nbr + (size_t)e1 * 64;
#pragma unroll
        for (int kk = 0; kk < 4; kk++) {
            int cA = 16 * kk + 2 * tig;
            float2 x0a = v0 ? *(const float2*)(r0 + cA)     : make_float2(0.f, 0.f);
            float2 x0b = v0 ? *(const float2*)(r0 + cA + 8) : make_float2(0.f, 0.f);
            float2 x1a = v1 ? *(const float2*)(r1 + cA)     : make_float2(0.f, 0.f);
            float2 x1b = v1 ? *(const float2*)(r1 + cA + 8) : make_float2(0.f, 0.f);
            uint32_t h;
            h = packbf(x0a.x, x0a.y); ah[kk*4+0] = h;
            { __nv_bfloat162 t = *(__nv_bfloat162*)&h;
              al[kk*4+0] = packbf(x0a.x - __bfloat162float(t.x), x0a.y - __bfloat162float(t.y)); }
            h = packbf(x1a.x, x1a.y); ah[kk*4+1] = h;
            { __nv_bfloat162 t = *(__nv_bfloat162*)&h;
              al[kk*4+1] = packbf(x1a.x - __bfloat162float(t.x), x1a.y - __bfloat162float(t.y)); }
            h = packbf(x0b.x, x0b.y); ah[kk*4+2] = h;
            { __nv_bfloat162 t = *(__nv_bfloat162*)&h;
              al[kk*4+2] = packbf(x0b.x - __bfloat162float(t.x), x0b.y - __bfloat162float(t.y)); }
            h = packbf(x1b.x, x1b.y); ah[kk*4+3] = h;
            { __nv_bfloat162 t = *(__nv_bfloat162*)&h;
              al[kk*4+3] = packbf(x1b.x - __bfloat162float(t.x), x1b.y - __bfloat162float(t.y)); }
        }
    }
    __syncthreads();

    // ---- mma mainloop: kk-outer, nt-inner (3-deep chains, 45 independent MMAs between revisits) ----
    float acc[64];
#pragma unroll
    for (int i = 0; i < 64; i++) acc[i] = 0.0f;

#pragma unroll
    for (int kk = 0; kk < 4; kk++) {
#pragma unroll
        for (int nt = 0; nt < 16; nt++) {
            float* c = acc + nt * 4;
            uint4 bw = s_w[(kk * 16 + nt) * 32 + lane];
            MMA_BF16(c, ah + kk * 4, bw.x, bw.y);   // Ah * Bh
            MMA_BF16(c, al + kk * 4, bw.x, bw.y);   // Al * Bh
            MMA_BF16(c, ah + kk * 4, bw.z, bw.w);   // Ah * Bl
        }
    }

    // ---- epilogue (interleaved pos layout; z stored fp16) ----
    int s0 = 0, d0 = 0, s1 = 0, d1 = 0;
    if (v0) { s0 = esrc[e0]; d0 = edst[e0]; }
    if (v1) { s1 = esrc[e1]; d1 = edst[e1]; }
    const int rep = (blockIdx.x ^ g) & (NREP - 1);
    float* gstat = g_stat[rep];

#pragma unroll
    for (int nt = 0; nt < 8; nt++) {
        const int i0 = 16 * nt + 4 * tig;
        float f0a = 0.f, c0a = 0.f, f1a = 0.f, c1a = 0.f;   // edge e0
        float f0b = 0.f, c0b = 0.f, f1b = 0.f, c1b = 0.f;   // edge e1
        if (v0) {
            float4 p1 = *(const float4*)&g_P[(size_t)s0 * 256 + i0];
            float4 p2 = *(const float4*)&g_P[(size_t)d0 * 256 + 128 + i0];
            f0a = acc[nt*4+0]     + p1.x + p2.x;
            c0a = acc[(nt+8)*4+0] + p1.y + p2.y;
            f1a = acc[nt*4+1]     + p1.z + p2.z;
            c1a = acc[(nt+8)*4+1] + p1.w + p2.w;
            *(uint2*)&g_zh[(size_t)e0 * 128 + i0] =
                make_uint2(packh2(f0a, c0a), packh2(f1a, c1a));
        }
        if (v1) {
            float4 p1 = *(const float4*)&g_P[(size_t)s1 * 256 + i0];
            float4 p2 = *(const float4*)&g_P[(size_t)d1 * 256 + 128 + i0];
            f0b = acc[nt*4+2]     + p1.x + p2.x;
            c0b = acc[(nt+8)*4+2] + p1.y + p2.y;
            f1b = acc[nt*4+3]     + p1.z + p2.z;
            c1b = acc[(nt+8)*4+3] + p1.w + p2.w;
            *(uint2*)&g_zh[(size_t)e1 * 128 + i0] =
                make_uint2(packh2(f0b, c0b), packh2(f1b, c1b));
        }
        float sf0 = f0a + f0b, qf0 = f0a * f0a + f0b * f0b;
        float sc0 = c0a + c0b, qc0 = c0a * c0a + c0b * c0b;
        float sf1 = f1a + f1b, qf1 = f1a * f1a + f1b * f1b;
        float sc1 = c1a + c1b, qc1 = c1a * c1a + c1b * c1b;
        asm volatile("red.global.add.v4.f32 [%0], {%1, %2, %3, %4};"
                     :: "l"(gstat + 2 * i0),     "f"(sf0), "f"(qf0), "f"(sc0), "f"(qc0) : "memory");
        asm volatile("red.global.add.v4.f32 [%0], {%1, %2, %3, %4};"
                     :: "l"(gstat + 2 * i0 + 4), "f"(sf1), "f"(qf1), "f"(sc1), "f"(qc1) : "memory");
    }
}

// ---------------------------------------------------------------- K3: BN1 finalize (emits pos-order scale/shift)
__global__ void k_bn1(const float* __restrict__ g1, const float* __restrict__ b1, int E) {
    int j = threadIdx.x;  // original column 0..127
    int base = (j < 64) ? 4 * j : 4 * (j - 64) + 2;
    double s = 0.0, q = 0.0;
    for (int r = 0; r < NREP; r++) {
        s += (double)g_stat[r][base];
        q += (double)g_stat[r][base + 1];
    }
    double mean = s / (double)E;
    double var  = q / (double)E - mean * mean;
    float istd = (float)rsqrt(var + 1e-5);
    float sc = g1[j] * istd;
    int pos = (j < 64) ? 2 * j : 2 * (j - 64) + 1;
    g_scale1[pos] = sc;
    g_shift1[pos] = b1[j] - (float)mean * sc;
}

// ---------------------------------------------------------------- K4: BN1 + gated message + scatter (fp16 z)
__global__ void k_msg(const int* __restrict__ edst, int E) {
    int gw = (int)((blockIdx.x * (size_t)blockDim.x + threadIdx.x) >> 5);
    int lane = threadIdx.x & 31;
    if (gw >= E) return;
    uint2 zr = *(const uint2*)&g_zh[(size_t)gw * 128 + 4 * lane];
    float2 z01 = __half22float2(*reinterpret_cast<__half2*>(&zr.x));  // {f0, c0}
    float2 z23 = __half22float2(*reinterpret_cast<__half2*>(&zr.y));  // {f1, c1}
    float4 sc = *(const float4*)&g_scale1[4 * lane];
    float4 sh = *(const float4*)&g_shift1[4 * lane];
    float m0 = sigmoidf(z01.x * sc.x + sh.x) * softplusf(z01.y * sc.y + sh.y);
    float m1 = sigmoidf(z23.x * sc.z + sh.z) * softplusf(z23.y * sc.w + sh.w);
    float sm0 = __shfl_xor_sync(0xFFFFFFFFu, m0, 1);
    float sm1 = __shfl_xor_sync(0xFFFFFFFFu, m1, 1);
    if ((lane & 1) == 0) {
        int d = edst[gw];
        float* p = &g_upd[(size_t)d * 64 + 2 * lane];
        asm volatile("red.global.add.v4.f32 [%0], {%1,%2,%3,%4};"
                     :: "l"(p), "f"(m0), "f"(m1), "f"(sm0), "f"(sm1) : "memory");
    }
}

// ---------------------------------------------------------------- K5: BN2 stats
__global__ void k_stats2(int N) {
    __shared__ double ssum[64], ssq[64];
    int tid = threadIdx.x;  // 256
    if (tid < 64) { ssum[tid] = 0.0; ssq[tid] = 0.0; }
    __syncthreads();
    int col = tid & 63;
    int r = blockIdx.x * 4 + (tid >> 6);
    float s = 0.0f, q = 0.0f;
    for (; r < N; r += gridDim.x * 4) {
        float v = g_upd[(size_t)r * 64 + col];
        s += v; q += v * v;
    }
    atomicAdd(&ssum[col], (double)s);
    atomicAdd(&ssq[col], (double)q);
    __syncthreads();
    if (tid < 64) {
        atomicAdd(&g_s2[tid], ssum[tid]);
        atomicAdd(&g_s2[64 + tid], ssq[tid]);
    }
}

// ---------------------------------------------------------------- K6: BN2 finalize
__global__ void k_bn2(const float* __restrict__ g2, const float* __restrict__ b2, int N) {
    int j = threadIdx.x;  // 64
    double mean = g_s2[j] / (double)N;
    double var  = g_s2[64 + j] / (double)N - mean * mean;
    float istd = (float)rsqrt(var + 1e-5);
    float sc = g2[j] * istd;
    g_scale2[j] = sc;
    g_shift2[j] = b2[j] - (float)mean * sc;
}

// ---------------------------------------------------------------- K7: output
__global__ void k_out(const float* __restrict__ atom, float* __restrict__ out, int N) {
    int i = blockIdx.x * blockDim.x + threadIdx.x;
    int total = N * 64;
    if (i >= total) return;
    int col = i & 63;
    float u = g_upd[i] * g_scale2[col] + g_shift2[col];
    out[i] = softplusf(atom[i] + u);
}

// ----------------------------------------------------------------
extern "C" void kernel_launch(void* const* d_in, const int* in_sizes, int n_in,
                              void* d_out, int out_size) {
    const float* atom = (const float*)d_in[0];
    const float* nbr  = (const float*)d_in[1];
    const int*   esrc = (const int*)d_in[2];
    const int*   edst = (const int*)d_in[3];
    const float* W    = (const float*)d_in[4];
    const float* b    = (const float*)d_in[5];
    const float* bn1g = (const float*)d_in[6];
    const float* bn1b = (const float*)d_in[7];
    const float* bn2g = (const float*)d_in[8];
    const float* bn2b = (const float*)d_in[9];
    float* out = (float*)d_out;

    int N = in_sizes[0] / 64;
    int E = in_sizes[2];
    int gE = (E + 127) / 128;

    k_zero<<<2048, 256>>>(N);
    k_prepW<<<8, 256>>>(W);
    dim3 gP(2, (N + 127) / 128);
    k_precompute<<<gP, 256>>>(atom, W, b, N);
    k_edge_mma<<<gE, 256>>>(nbr, esrc, edst, E);
    k_bn1<<<1, 128>>>(bn1g, bn1b, E);
    {
        long long threads = (long long)E * 32;
        int grid = (int)((threads + 255) / 256);
        k_msg<<<grid, 256>>>(edst, E);
    }
    k_stats2<<<128, 256>>>(N);
    k_bn2<<<1, 64>>>(bn2g, bn2b, N);
    k_out<<<(N * 64 + 255) / 256, 256>>>(atom, out, N);
}